// round 1
// baseline (speedup 1.0000x reference)
#include <cuda_runtime.h>
#include <cstdint>
#include <cstddef>

// Problem constants (fixed shapes for this problem)
#define Mtot   8192
#define Ltot   256
#define Qd     21
#define QQ     441            // Q*Q
#define TILE_M 512
#define JC     8              // j's per chunk
#define NMT    (Mtot / TILE_M)        // 16
#define NBLK_MAIN (Ltot * NMT)        // 4096
#define NBLK_REGJ 2048
#define LAMBDA_H_F 1e-6f
#define LAMBDA_J_F 1e-4f

// Static device scratch (no runtime allocation allowed)
__device__ unsigned char g_X8[Mtot * Ltot];       // 2 MB: X as uint8, [m][j]
__device__ float g_partial[NBLK_MAIN];            // per-CTA NLL partials
__device__ float g_regj[NBLK_REGJ];               // regJ partials

// ---------------------------------------------------------------------------
// Kernel 1: convert X_idx (int32) -> uint8, same [m][j] layout
// ---------------------------------------------------------------------------
__global__ void k_x8(const int* __restrict__ X) {
    int t = blockIdx.x * blockDim.x + threadIdx.x;
    if (t < Mtot * Ltot) g_X8[t] = (unsigned char)X[t];
}

// ---------------------------------------------------------------------------
// Kernel 2: regJ = sum over strictly-lower (j<i) blocks of J^2 (partials)
// ---------------------------------------------------------------------------
__global__ void k_regj(const float* __restrict__ J) {
    const unsigned total = (unsigned)Ltot * (unsigned)Ltot * (unsigned)QQ; // 28.9M < 2^31
    float s = 0.f;
    for (unsigned t = blockIdx.x * blockDim.x + threadIdx.x; t < total;
         t += gridDim.x * blockDim.x) {
        unsigned blk = t / QQ;          // const divide -> mul/shift
        unsigned j = blk & (Ltot - 1);
        unsigned i = blk >> 8;
        if (j < i) { float v = J[t]; s += v * v; }
    }
    #pragma unroll
    for (int o = 16; o; o >>= 1) s += __shfl_xor_sync(0xffffffffu, s, o);
    __shared__ float red[8];
    if ((threadIdx.x & 31) == 0) red[threadIdx.x >> 5] = s;
    __syncthreads();
    if (threadIdx.x == 0) {
        float t = 0.f;
        #pragma unroll
        for (int k = 0; k < 8; ++k) t += red[k];
        g_regj[blockIdx.x] = t;
    }
}

// ---------------------------------------------------------------------------
// Kernel 3: main gather kernel. CTA = (position i, tile of 512 m).
// ---------------------------------------------------------------------------
__device__ __forceinline__ void cp_async16(void* s, const void* g) {
    unsigned sa = (unsigned)__cvta_generic_to_shared(s);
    asm volatile("cp.async.cg.shared.global [%0], [%1], 16;" :: "r"(sa), "l"(g));
}

__global__ void __launch_bounds__(TILE_M, 2) k_main(
    const float* __restrict__ W,
    const float* __restrict__ h,
    const float* __restrict__ J)
{
    __shared__ float sJ[2][JC * QQ];   // 2 * 14112 B, double buffer
    __shared__ float sH[Qd];
    __shared__ float sRed[TILE_M / 32];

    const int bid = blockIdx.x;
    const int i   = (Ltot - 1) - (bid >> 4);   // descending i: big work first
    const int mt  = bid & (NMT - 1);
    const int tid = threadIdx.x;
    const int m   = mt * TILE_M + tid;

    if (tid < Qd) sH[tid] = h[i * Qd + tid];

    const float* Jrow = J + (size_t)i * (size_t)(Ltot * QQ);
    const int full = i >> 3;
    const int rem  = i & 7;
    const int nc   = full + (rem ? 1 : 0);

    // Prologue: issue chunk 0 (always loads a full 8-j block; valid since
    // row i spans j in [0,256) and j0+7 <= 255 for all chunks we touch).
    if (nc > 0) {
        const float4* src = (const float4*)Jrow;
        float4* dst = (float4*)sJ[0];
        #pragma unroll
        for (int k = 0; k < 2; ++k) {
            int idx = tid + k * TILE_M;
            if (idx < (JC * QQ) / 4) cp_async16(dst + idx, src + idx);
        }
    }
    asm volatile("cp.async.commit_group;");
    __syncthreads();

    float acc[Qd];
    #pragma unroll
    for (int a = 0; a < Qd; ++a) acc[a] = sH[a];

    const unsigned char* xrow = g_X8 + (size_t)m * Ltot;

    for (int c = 0; c < nc; ++c) {
        const int buf = c & 1;
        // prefetch next chunk into the other buffer
        if (c + 1 < nc) {
            const float4* src = (const float4*)(Jrow + (size_t)(c + 1) * (JC * QQ));
            float4* dst = (float4*)sJ[buf ^ 1];
            #pragma unroll
            for (int k = 0; k < 2; ++k) {
                int idx = tid + k * TILE_M;
                if (idx < (JC * QQ) / 4) cp_async16(dst + idx, src + idx);
            }
        }
        asm volatile("cp.async.commit_group;");

        // per-thread X bytes for this chunk (independent global load, 8B aligned)
        unsigned long long xb = *(const unsigned long long*)(xrow + c * JC);

        if (c + 1 < nc) { asm volatile("cp.async.wait_group 1;"); }
        else            { asm volatile("cp.async.wait_group 0;"); }
        __syncthreads();

        const float* base = sJ[buf];
        const int cnt = (c == full) ? rem : JC;
        if (cnt == JC) {
            #pragma unroll
            for (int jj = 0; jj < JC; ++jj) {
                const int b = (int)((xb >> (8 * jj)) & 0xffull);
                const float* p = base + jj * QQ + b;
                #pragma unroll
                for (int a = 0; a < Qd; ++a) acc[a] += p[a * Qd];
            }
        } else {
            for (int jj = 0; jj < cnt; ++jj) {
                const int b = (int)((xb >> (8 * jj)) & 0xffull);
                const float* p = base + jj * QQ + b;
                #pragma unroll
                for (int a = 0; a < Qd; ++a) acc[a] += p[a * Qd];
            }
        }
        __syncthreads();
    }

    // Epilogue: -gold_logp = logsumexp(acc) - acc[b_i], weighted by W[m]
    const int bi  = (int)xrow[i];
    const float w = W[m];
    float mx = acc[0];
    #pragma unroll
    for (int a = 1; a < Qd; ++a) mx = fmaxf(mx, acc[a]);
    float s = 0.f, gold = 0.f;
    #pragma unroll
    for (int a = 0; a < Qd; ++a) {
        float e = acc[a] - mx;
        s += __expf(e);
        if (a == bi) gold = e;
    }
    float v = w * (__logf(s) - gold);

    #pragma unroll
    for (int o = 16; o; o >>= 1) v += __shfl_xor_sync(0xffffffffu, v, o);
    if ((tid & 31) == 0) sRed[tid >> 5] = v;
    __syncthreads();
    if (tid == 0) {
        float t = 0.f;
        #pragma unroll
        for (int k = 0; k < TILE_M / 32; ++k) t += sRed[k];
        g_partial[bid] = t;
    }
}

// ---------------------------------------------------------------------------
// Kernel 4: final deterministic reduction + regularizers
// ---------------------------------------------------------------------------
__global__ void k_final(const float* __restrict__ h, float* __restrict__ out) {
    const int tid = threadIdx.x;
    float v = 0.f;
    for (int t = tid; t < NBLK_MAIN; t += 1024) v += g_partial[t];
    float rj = 0.f;
    for (int t = tid; t < NBLK_REGJ; t += 1024) rj += g_regj[t];
    float rh = 0.f;
    for (int t = tid; t < Ltot * Qd; t += 1024) { float x = h[t]; rh += x * x; }
    float r = v + LAMBDA_J_F * rj + LAMBDA_H_F * rh;
    #pragma unroll
    for (int o = 16; o; o >>= 1) r += __shfl_xor_sync(0xffffffffu, r, o);
    __shared__ float red[32];
    if ((tid & 31) == 0) red[tid >> 5] = r;
    __syncthreads();
    if (tid == 0) {
        float t = 0.f;
        #pragma unroll
        for (int k = 0; k < 32; ++k) t += red[k];
        out[0] = t;
    }
}

// ---------------------------------------------------------------------------
// Launch
// ---------------------------------------------------------------------------
extern "C" void kernel_launch(void* const* d_in, const int* in_sizes, int n_in,
                              void* d_out, int out_size) {
    const int*   X = (const int*)d_in[0];      // (M, L) int32
    const float* W = (const float*)d_in[1];    // (M,)
    const float* h = (const float*)d_in[2];    // (L, Q)
    const float* J = (const float*)d_in[3];    // (L, L, Q, Q)
    float* out = (float*)d_out;

    k_x8  <<<(Mtot * Ltot + 255) / 256, 256>>>(X);
    k_regj<<<NBLK_REGJ, 256>>>(J);
    k_main<<<NBLK_MAIN, TILE_M>>>(W, h, J);
    k_final<<<1, 1024>>>(h, out);
}

// round 2
// speedup vs baseline: 1.3010x; 1.3010x over previous
#include <cuda_runtime.h>
#include <cuda_bf16.h>
#include <cstdint>
#include <cstddef>

// Problem constants (fixed shapes)
#define Mtot   8192
#define Ltot   256
#define Qd     21
#define QQ     441
#define APAD   22              // a padded to 22 (11 bf16x2 words)
#define JPB    464             // bf16 per (i,j) block: 21*22=462 -> pad to 464 (928 B, 16B mult)
#define TILE_M 512
#define JC     8               // j's per chunk
#define NMT    (Mtot / TILE_M)         // 16
#define NBLK_MAIN (Ltot * NMT)         // 4096
#define NPAIR  (Ltot * Ltot)           // 65536
#define LAMBDA_H_F 1e-6f
#define LAMBDA_J_F 1e-4f

// Static device scratch
__device__ unsigned char g_X8[Mtot * Ltot];                 // 2 MB
__device__ __nv_bfloat16 g_Jb[(size_t)NPAIR * JPB];         // 58 MB transposed bf16 J
__device__ float g_partial[NBLK_MAIN];
__device__ float g_regjT[NPAIR];

// ---------------------------------------------------------------------------
// Kernel 1: X int32 -> uint8
// ---------------------------------------------------------------------------
__global__ void k_x8(const int* __restrict__ X) {
    int t = blockIdx.x * blockDim.x + threadIdx.x;
    if (t < Mtot * Ltot) g_X8[t] = (unsigned char)X[t];
}

// ---------------------------------------------------------------------------
// Kernel 2: per-(i,j) transpose J[a][b] -> bf16 [b][a_pad], + regJ partials.
// One 128-thread block per (i,j). j >= i blocks: write 0 regj, skip transpose
// (g_Jb stays zero-initialized there and is never accumulated).
// ---------------------------------------------------------------------------
__global__ void __launch_bounds__(128) k_prep(const float* __restrict__ J) {
    const int blk = blockIdx.x;
    const int i = blk >> 8, j = blk & 255;
    const int tid = threadIdx.x;
    __shared__ float s[QQ];
    __shared__ float red[4];

    if (j >= i) {
        if (tid == 0) g_regjT[blk] = 0.f;
        return;
    }

    float sq = 0.f;
    for (int t = tid; t < QQ; t += 128) {
        float v = J[(size_t)blk * QQ + t];
        s[t] = v;
        sq += v * v;
    }
    #pragma unroll
    for (int o = 16; o; o >>= 1) sq += __shfl_xor_sync(0xffffffffu, sq, o);
    if ((tid & 31) == 0) red[tid >> 5] = sq;
    __syncthreads();
    if (tid == 0) g_regjT[blk] = red[0] + red[1] + red[2] + red[3];

    __nv_bfloat16* dst = g_Jb + (size_t)blk * JPB;
    for (int t = tid; t < JPB; t += 128) {
        int b = t / APAD;
        int a = t - b * APAD;
        float v = (t < Qd * APAD && a < Qd) ? s[a * Qd + b] : 0.f;
        dst[t] = __float2bfloat16(v);
    }
}

// ---------------------------------------------------------------------------
// Kernel 3: main gather. CTA = (position i, tile of 512 m).
// SMEM holds bf16 [jj][b][a_pad]; per (thread,j): 11 LDS.32 -> 11 f32x2 adds.
// ---------------------------------------------------------------------------
__device__ __forceinline__ void cp_async16(void* s, const void* g) {
    unsigned sa = (unsigned)__cvta_generic_to_shared(s);
    asm volatile("cp.async.cg.shared.global [%0], [%1], 16;" :: "r"(sa), "l"(g));
}

#define CHUNK_BF16 (JC * JPB)          // 3712 bf16 = 7424 B = 464 x 16B

__global__ void __launch_bounds__(TILE_M, 2) k_main(
    const float* __restrict__ W,
    const float* __restrict__ h)
{
    __shared__ __align__(16) __nv_bfloat16 sJ[2][CHUNK_BF16];
    __shared__ float sH[APAD];
    __shared__ float sRed[TILE_M / 32];

    const int bid = blockIdx.x;
    const int i   = (Ltot - 1) - (bid >> 4);   // descending i: big work first
    const int mt  = bid & (NMT - 1);
    const int tid = threadIdx.x;
    const int m   = mt * TILE_M + tid;

    if (tid < APAD) sH[tid] = (tid < Qd) ? h[i * Qd + tid] : 0.f;

    const __nv_bfloat16* Jrow = g_Jb + (size_t)i * (Ltot * JPB);
    const int full = i >> 3;
    const int rem  = i & 7;
    const int nc   = full + (rem ? 1 : 0);

    if (nc > 0) {
        const float4* src = (const float4*)Jrow;
        float4* dst = (float4*)sJ[0];
        if (tid < CHUNK_BF16 / 8) cp_async16(dst + tid, src + tid);
    }
    asm volatile("cp.async.commit_group;");
    __syncthreads();

    // 11 packed f32x2 accumulators (a, a+1); slot a=21 is pad (h pad = 0, J pad = 0)
    uint64_t acc2[11];
    #pragma unroll
    for (int k = 0; k < 11; ++k) {
        uint32_t lo = __float_as_uint(sH[2 * k]);
        uint32_t hi = __float_as_uint(sH[2 * k + 1]);
        asm("mov.b64 %0, {%1, %2};" : "=l"(acc2[k]) : "r"(lo), "r"(hi));
    }

    const unsigned char* xrow = g_X8 + (size_t)m * Ltot;

    for (int c = 0; c < nc; ++c) {
        const int buf = c & 1;
        if (c + 1 < nc) {
            const float4* src = (const float4*)(Jrow + (size_t)(c + 1) * CHUNK_BF16);
            float4* dst = (float4*)sJ[buf ^ 1];
            if (tid < CHUNK_BF16 / 8) cp_async16(dst + tid, src + tid);
        }
        asm volatile("cp.async.commit_group;");

        unsigned long long xb = *(const unsigned long long*)(xrow + c * JC);

        if (c + 1 < nc) { asm volatile("cp.async.wait_group 1;"); }
        else            { asm volatile("cp.async.wait_group 0;"); }
        __syncthreads();

        const uint32_t* base32 = (const uint32_t*)sJ[buf];
        const int cnt = (c == full) ? rem : JC;

        if (cnt == JC) {
            #pragma unroll
            for (int jj = 0; jj < JC; ++jj) {
                const int b = (int)((xb >> (8 * jj)) & 0xffull);
                const uint32_t* p = base32 + jj * (JPB / 2) + b * (APAD / 2);
                #pragma unroll
                for (int k = 0; k < 11; ++k) {
                    uint32_t u  = p[k];
                    uint32_t lo = u << 16;
                    uint32_t hi = u & 0xffff0000u;
                    uint64_t v;
                    asm("mov.b64 %0, {%1, %2};" : "=l"(v) : "r"(lo), "r"(hi));
                    asm("add.rn.f32x2 %0, %0, %1;" : "+l"(acc2[k]) : "l"(v));
                }
            }
        } else {
            for (int jj = 0; jj < cnt; ++jj) {
                const int b = (int)((xb >> (8 * jj)) & 0xffull);
                const uint32_t* p = base32 + jj * (JPB / 2) + b * (APAD / 2);
                #pragma unroll
                for (int k = 0; k < 11; ++k) {
                    uint32_t u  = p[k];
                    uint32_t lo = u << 16;
                    uint32_t hi = u & 0xffff0000u;
                    uint64_t v;
                    asm("mov.b64 %0, {%1, %2};" : "=l"(v) : "r"(lo), "r"(hi));
                    asm("add.rn.f32x2 %0, %0, %1;" : "+l"(acc2[k]) : "l"(v));
                }
            }
        }
        __syncthreads();
    }

    // Unpack accumulators
    float acc[Qd];
    #pragma unroll
    for (int k = 0; k < 11; ++k) {
        uint32_t lo, hi;
        asm("mov.b64 {%0, %1}, %2;" : "=r"(lo), "=r"(hi) : "l"(acc2[k]));
        acc[2 * k] = __uint_as_float(lo);
        if (2 * k + 1 < Qd) acc[2 * k + 1] = __uint_as_float(hi);
    }

    // Epilogue: w * (logsumexp(acc) - acc[gold])
    const int bi  = (int)xrow[i];
    const float w = W[m];
    float mx = acc[0];
    #pragma unroll
    for (int a = 1; a < Qd; ++a) mx = fmaxf(mx, acc[a]);
    float s = 0.f, gold = 0.f;
    #pragma unroll
    for (int a = 0; a < Qd; ++a) {
        float e = acc[a] - mx;
        s += __expf(e);
        if (a == bi) gold = e;
    }
    float v = w * (__logf(s) - gold);

    #pragma unroll
    for (int o = 16; o; o >>= 1) v += __shfl_xor_sync(0xffffffffu, v, o);
    if ((tid & 31) == 0) sRed[tid >> 5] = v;
    __syncthreads();
    if (tid == 0) {
        float t = 0.f;
        #pragma unroll
        for (int k = 0; k < TILE_M / 32; ++k) t += sRed[k];
        g_partial[bid] = t;
    }
}

// ---------------------------------------------------------------------------
// Kernel 4: final deterministic reduction + regularizers
// ---------------------------------------------------------------------------
__global__ void k_final(const float* __restrict__ h, float* __restrict__ out) {
    const int tid = threadIdx.x;
    float v = 0.f;
    for (int t = tid; t < NBLK_MAIN; t += 1024) v += g_partial[t];
    float rj = 0.f;
    for (int t = tid; t < NPAIR; t += 1024) rj += g_regjT[t];
    float rh = 0.f;
    for (int t = tid; t < Ltot * Qd; t += 1024) { float x = h[t]; rh += x * x; }
    float r = v + LAMBDA_J_F * rj + LAMBDA_H_F * rh;
    #pragma unroll
    for (int o = 16; o; o >>= 1) r += __shfl_xor_sync(0xffffffffu, r, o);
    __shared__ float red[32];
    if ((tid & 31) == 0) red[tid >> 5] = r;
    __syncthreads();
    if (tid == 0) {
        float t = 0.f;
        #pragma unroll
        for (int k = 0; k < 32; ++k) t += red[k];
        out[0] = t;
    }
}

// ---------------------------------------------------------------------------
// Launch
// ---------------------------------------------------------------------------
extern "C" void kernel_launch(void* const* d_in, const int* in_sizes, int n_in,
                              void* d_out, int out_size) {
    const int*   X = (const int*)d_in[0];      // (M, L) int32
    const float* W = (const float*)d_in[1];    // (M,)
    const float* h = (const float*)d_in[2];    // (L, Q)
    const float* J = (const float*)d_in[3];    // (L, L, Q, Q)
    float* out = (float*)d_out;

    k_x8   <<<(Mtot * Ltot + 255) / 256, 256>>>(X);
    k_prep <<<NPAIR, 128>>>(J);
    k_main <<<NBLK_MAIN, TILE_M>>>(W, h);
    k_final<<<1, 1024>>>(h, out);
}

// round 3
// speedup vs baseline: 1.6519x; 1.2697x over previous
#include <cuda_runtime.h>
#include <cuda_fp16.h>
#include <cstdint>
#include <cstddef>

// Problem constants (fixed shapes)
#define Mtot   8192
#define Ltot   256
#define Qd     21
#define QQ     441
#define APAD   22              // a padded to 22 (11 half2 words)
#define JPB    464             // fp16 per (i,j) block: 21*22=462 -> pad 464 (928 B)
#define TILE_M 512
#define JC     16              // j's per chunk
#define NMT    (Mtot / TILE_M)         // 16
#define NBLK_MAIN (Ltot * NMT)         // 4096
#define NPAIR  (Ltot * Ltot)           // 65536
#define LAMBDA_H_F 1e-6f
#define LAMBDA_J_F 1e-4f

// Static device scratch
__device__ unsigned char g_X8[Mtot * Ltot];           // 2 MB
__device__ __half g_Jh[(size_t)NPAIR * JPB];          // 58 MB transposed fp16 J
__device__ float g_partial[NBLK_MAIN];
__device__ float g_regjT[NPAIR];

// ---------------------------------------------------------------------------
// Kernel 1: X int32 -> uint8
// ---------------------------------------------------------------------------
__global__ void k_x8(const int* __restrict__ X) {
    int t = blockIdx.x * blockDim.x + threadIdx.x;
    if (t < Mtot * Ltot) g_X8[t] = (unsigned char)X[t];
}

// ---------------------------------------------------------------------------
// Kernel 2: per-(i,j) transpose J[a][b] -> fp16 [b][a_pad], + regJ partials.
// ---------------------------------------------------------------------------
__global__ void __launch_bounds__(128) k_prep(const float* __restrict__ J) {
    const int blk = blockIdx.x;
    const int i = blk >> 8, j = blk & 255;
    const int tid = threadIdx.x;
    __shared__ float s[QQ];
    __shared__ float red[4];

    if (j >= i) {
        if (tid == 0) g_regjT[blk] = 0.f;
        return;
    }

    float sq = 0.f;
    for (int t = tid; t < QQ; t += 128) {
        float v = J[(size_t)blk * QQ + t];
        s[t] = v;
        sq += v * v;
    }
    #pragma unroll
    for (int o = 16; o; o >>= 1) sq += __shfl_xor_sync(0xffffffffu, sq, o);
    if ((tid & 31) == 0) red[tid >> 5] = sq;
    __syncthreads();
    if (tid == 0) g_regjT[blk] = red[0] + red[1] + red[2] + red[3];

    __half* dst = g_Jh + (size_t)blk * JPB;
    for (int t = tid; t < JPB; t += 128) {
        int b = t / APAD;
        int a = t - b * APAD;
        float v = (t < Qd * APAD && a < Qd) ? s[a * Qd + b] : 0.f;
        dst[t] = __float2half(v);
    }
}

// ---------------------------------------------------------------------------
// Kernel 3: main gather. CTA = (position i, tile of 512 m).
// Inner body per (thread, j, k): LDS.32 (half2) + HADD2. Flush to fp32 per chunk.
// ---------------------------------------------------------------------------
__device__ __forceinline__ void cp_async16(void* s, const void* g) {
    unsigned sa = (unsigned)__cvta_generic_to_shared(s);
    asm volatile("cp.async.cg.shared.global [%0], [%1], 16;" :: "r"(sa), "l"(g));
}

#define CHUNK_HALF (JC * JPB)            // 7424 half = 14848 B = 928 x 16B
#define CHUNK_F4   (CHUNK_HALF / 8)      // 928

__global__ void __launch_bounds__(TILE_M, 2) k_main(
    const float* __restrict__ W,
    const float* __restrict__ h)
{
    __shared__ __align__(16) __half sJ[2][CHUNK_HALF];
    __shared__ float sH[APAD];
    __shared__ float sRed[TILE_M / 32];

    const int bid = blockIdx.x;
    const int i   = (Ltot - 1) - (bid >> 4);   // descending i: big work first
    const int mt  = bid & (NMT - 1);
    const int tid = threadIdx.x;
    const int m   = mt * TILE_M + tid;

    if (tid < APAD) sH[tid] = (tid < Qd) ? h[i * Qd + tid] : 0.f;

    const __half* Jrow = g_Jh + (size_t)i * (Ltot * JPB);
    const int full = i >> 4;
    const int rem  = i & 15;
    const int nc   = full + (rem ? 1 : 0);

    if (nc > 0) {
        const float4* src = (const float4*)Jrow;
        float4* dst = (float4*)sJ[0];
        #pragma unroll
        for (int k = 0; k < 2; ++k) {
            int idx = tid + k * TILE_M;
            if (idx < CHUNK_F4) cp_async16(dst + idx, src + idx);
        }
    }
    asm volatile("cp.async.commit_group;");
    __syncthreads();

    // fp32 accumulators as 11 packed f32x2 (slot a=21 is pad; h pad = 0, J pad = 0)
    uint64_t acc2[11];
    #pragma unroll
    for (int k = 0; k < 11; ++k) {
        uint32_t lo = __float_as_uint(sH[2 * k]);
        uint32_t hi = __float_as_uint(sH[2 * k + 1]);
        asm("mov.b64 %0, {%1, %2};" : "=l"(acc2[k]) : "r"(lo), "r"(hi));
    }

    const unsigned char* xrow = g_X8 + (size_t)m * Ltot;

    for (int c = 0; c < nc; ++c) {
        const int buf = c & 1;
        if (c + 1 < nc) {
            const float4* src = (const float4*)(Jrow + (size_t)(c + 1) * CHUNK_HALF);
            float4* dst = (float4*)sJ[buf ^ 1];
            #pragma unroll
            for (int k = 0; k < 2; ++k) {
                int idx = tid + k * TILE_M;
                if (idx < CHUNK_F4) cp_async16(dst + idx, src + idx);
            }
        }
        asm volatile("cp.async.commit_group;");

        // 16 X bytes for this chunk (16B-aligned)
        const uint4 xv = *(const uint4*)(xrow + c * JC);

        if (c + 1 < nc) { asm volatile("cp.async.wait_group 1;"); }
        else            { asm volatile("cp.async.wait_group 0;"); }
        __syncthreads();

        const __half2* base = (const __half2*)sJ[buf];
        const int cnt = (c == full) ? rem : JC;

        // fp16x2 chunk accumulators
        __half2 hacc[11];
        #pragma unroll
        for (int k = 0; k < 11; ++k) hacc[k] = __half2half2(__ushort_as_half(0));

        if (cnt == JC) {
            const uint32_t xw[4] = {xv.x, xv.y, xv.z, xv.w};
            #pragma unroll
            for (int w = 0; w < 4; ++w) {
                #pragma unroll
                for (int s = 0; s < 4; ++s) {
                    const int jj = w * 4 + s;
                    const int b = (int)((xw[w] >> (8 * s)) & 0xffu);
                    const __half2* p = base + jj * (JPB / 2) + b * (APAD / 2);
                    #pragma unroll
                    for (int k = 0; k < 11; ++k) hacc[k] = __hadd2(hacc[k], p[k]);
                }
            }
        } else {
            const uint32_t xw[4] = {xv.x, xv.y, xv.z, xv.w};
            for (int jj = 0; jj < cnt; ++jj) {
                const int b = (int)((xw[jj >> 2] >> (8 * (jj & 3))) & 0xffu);
                const __half2* p = base + jj * (JPB / 2) + b * (APAD / 2);
                #pragma unroll
                for (int k = 0; k < 11; ++k) hacc[k] = __hadd2(hacc[k], p[k]);
            }
        }

        // Flush chunk partials into fp32 accumulators
        #pragma unroll
        for (int k = 0; k < 11; ++k) {
            float2 f = __half22float2(hacc[k]);
            uint64_t v;
            asm("mov.b64 %0, {%1, %2};" : "=l"(v)
                : "r"(__float_as_uint(f.x)), "r"(__float_as_uint(f.y)));
            asm("add.rn.f32x2 %0, %0, %1;" : "+l"(acc2[k]) : "l"(v));
        }
        __syncthreads();
    }

    // Unpack accumulators
    float acc[Qd];
    #pragma unroll
    for (int k = 0; k < 11; ++k) {
        uint32_t lo, hi;
        asm("mov.b64 {%0, %1}, %2;" : "=r"(lo), "=r"(hi) : "l"(acc2[k]));
        acc[2 * k] = __uint_as_float(lo);
        if (2 * k + 1 < Qd) acc[2 * k + 1] = __uint_as_float(hi);
    }

    // Epilogue: w * (logsumexp(acc) - acc[gold])
    const int bi  = (int)xrow[i];
    const float w = W[m];
    float mx = acc[0];
    #pragma unroll
    for (int a = 1; a < Qd; ++a) mx = fmaxf(mx, acc[a]);
    float s = 0.f, gold = 0.f;
    #pragma unroll
    for (int a = 0; a < Qd; ++a) {
        float e = acc[a] - mx;
        s += __expf(e);
        if (a == bi) gold = e;
    }
    float v = w * (__logf(s) - gold);

    #pragma unroll
    for (int o = 16; o; o >>= 1) v += __shfl_xor_sync(0xffffffffu, v, o);
    if ((tid & 31) == 0) sRed[tid >> 5] = v;
    __syncthreads();
    if (tid == 0) {
        float t = 0.f;
        #pragma unroll
        for (int k = 0; k < TILE_M / 32; ++k) t += sRed[k];
        g_partial[bid] = t;
    }
}

// ---------------------------------------------------------------------------
// Kernel 4: final deterministic reduction + regularizers
// ---------------------------------------------------------------------------
__global__ void k_final(const float* __restrict__ h, float* __restrict__ out) {
    const int tid = threadIdx.x;
    float v = 0.f;
    for (int t = tid; t < NBLK_MAIN; t += 1024) v += g_partial[t];
    float rj = 0.f;
    for (int t = tid; t < NPAIR; t += 1024) rj += g_regjT[t];
    float rh = 0.f;
    for (int t = tid; t < Ltot * Qd; t += 1024) { float x = h[t]; rh += x * x; }
    float r = v + LAMBDA_J_F * rj + LAMBDA_H_F * rh;
    #pragma unroll
    for (int o = 16; o; o >>= 1) r += __shfl_xor_sync(0xffffffffu, r, o);
    __shared__ float red[32];
    if ((tid & 31) == 0) red[tid >> 5] = r;
    __syncthreads();
    if (tid == 0) {
        float t = 0.f;
        #pragma unroll
        for (int k = 0; k < 32; ++k) t += red[k];
        out[0] = t;
    }
}

// ---------------------------------------------------------------------------
// Launch
// ---------------------------------------------------------------------------
extern "C" void kernel_launch(void* const* d_in, const int* in_sizes, int n_in,
                              void* d_out, int out_size) {
    const int*   X = (const int*)d_in[0];      // (M, L) int32
    const float* W = (const float*)d_in[1];    // (M,)
    const float* h = (const float*)d_in[2];    // (L, Q)
    const float* J = (const float*)d_in[3];    // (L, L, Q, Q)
    float* out = (float*)d_out;

    k_x8   <<<(Mtot * Ltot + 255) / 256, 256>>>(X);
    k_prep <<<NPAIR, 128>>>(J);
    k_main <<<NBLK_MAIN, TILE_M>>>(W, h);
    k_final<<<1, 1024>>>(h, out);
}